// round 5
// baseline (speedup 1.0000x reference)
#include <cuda_runtime.h>
#include <cuda_bf16.h>
#include <cstdint>

// Problem constants
#define BATCH 2
#define SEQ   2048
#define DMODEL 1024
#define NHEAD 16
#define HDIM  64
#define ROWS  (BATCH*SEQ)          // 4096
#define ELEMS (ROWS*DMODEL)        // 4,194,304
#define KEFF  3072                 // 3-term bf16 split K

// Scratch (static __device__ globals — allocation-free per harness rules)
__device__ float g_k[ELEMS];   // masked K (K')
__device__ float g_v[ELEMS];
__device__ float g_m[BATCH*NHEAD*HDIM*HDIM];   // 131072 floats
__device__ float g_bias_ctx[BATCH*DMODEL];
__device__ __nv_bfloat16 g_abar[(size_t)ROWS*KEFF];        // X split   24MB
__device__ __nv_bfloat16 g_bbar[(size_t)4*DMODEL*KEFF];    // Wk,Wv,Bctx0,Bctx1 24MB

// ---------------------------------------------------------------------------
// Base-target (sm_80+) PTX helpers: ldmatrix / mma.sync / cp.async
// ---------------------------------------------------------------------------
__device__ __forceinline__ uint32_t smem_to_u32(const void* p) {
    uint32_t a;
    asm("{ .reg .u64 t; cvta.to.shared.u64 t, %1; cvt.u32.u64 %0, t; }" : "=r"(a) : "l"(p));
    return a;
}
__device__ __forceinline__ void ldsm_x4(uint32_t& r0, uint32_t& r1, uint32_t& r2, uint32_t& r3,
                                        uint32_t addr) {
    asm volatile("ldmatrix.sync.aligned.m8n8.x4.shared.b16 {%0,%1,%2,%3}, [%4];"
                 : "=r"(r0), "=r"(r1), "=r"(r2), "=r"(r3) : "r"(addr));
}
__device__ __forceinline__ void mma_bf16(float* d, uint32_t a0, uint32_t a1, uint32_t a2,
                                         uint32_t a3, uint32_t b0, uint32_t b1) {
    asm volatile("mma.sync.aligned.m16n8k16.row.col.f32.bf16.bf16.f32 "
                 "{%0,%1,%2,%3}, {%4,%5,%6,%7}, {%8,%9}, {%0,%1,%2,%3};"
                 : "+f"(d[0]), "+f"(d[1]), "+f"(d[2]), "+f"(d[3])
                 : "r"(a0), "r"(a1), "r"(a2), "r"(a3), "r"(b0), "r"(b1));
}
#define CP_ASYNC16(saddr, gptr) \
    asm volatile("cp.async.cg.shared.global [%0], [%1], 16;" :: "r"(saddr), "l"(gptr))
#define CP_COMMIT() asm volatile("cp.async.commit_group;" ::: "memory")
#define CP_WAIT1()  asm volatile("cp.async.wait_group 1;" ::: "memory")
#define CP_WAIT0()  asm volatile("cp.async.wait_group 0;" ::: "memory")

// SW128 swizzle: rows of 128B, chunk16B index ^= (row & 7)
#define SWZ128(bo) ((bo) ^ (((bo) >> 3) & 0x70))

// ---------------------------------------------------------------------------
// node 0: X -> Abar = [hi | lo | hi] along K (bf16 split)
// ---------------------------------------------------------------------------
__global__ __launch_bounds__(256) void conv_x(const float* __restrict__ X)
{
    int t = blockIdx.x * 256 + threadIdx.x;
    int idx = t * 4;
    float4 v = *(const float4*)(X + idx);
    int r = idx >> 10, k = idx & 1023;
    float f[4] = {v.x, v.y, v.z, v.w};
    __nv_bfloat16 h[4], l[4];
#pragma unroll
    for (int i = 0; i < 4; i++) {
        h[i] = __float2bfloat16(f[i]);
        l[i] = __float2bfloat16(f[i] - __bfloat162float(h[i]));
    }
    __nv_bfloat16* base = g_abar + (size_t)r * KEFF;
    *(__nv_bfloat162*)(base + k)          = __nv_bfloat162(h[0], h[1]);
    *(__nv_bfloat162*)(base + k + 2)      = __nv_bfloat162(h[2], h[3]);
    *(__nv_bfloat162*)(base + 1024 + k)   = __nv_bfloat162(l[0], l[1]);
    *(__nv_bfloat162*)(base + 1024 + k+2) = __nv_bfloat162(l[2], l[3]);
    *(__nv_bfloat162*)(base + 2048 + k)   = __nv_bfloat162(h[0], h[1]);
    *(__nv_bfloat162*)(base + 2048 + k+2) = __nv_bfloat162(h[2], h[3]);
}

// node 1: Wk,Wv -> Bbar slabs 0,1 = [hi | hi | lo]
__global__ __launch_bounds__(256) void conv_w(const float* __restrict__ Wk,
                                              const float* __restrict__ Wv)
{
    int which = blockIdx.y;
    const float* __restrict__ W = (which == 0) ? Wk : Wv;
    int t = blockIdx.x * 256 + threadIdx.x;
    int idx = t * 4;
    float4 v = *(const float4*)(W + idx);
    int r = idx >> 10, k = idx & 1023;
    float f[4] = {v.x, v.y, v.z, v.w};
    __nv_bfloat16 h[4], l[4];
#pragma unroll
    for (int i = 0; i < 4; i++) {
        h[i] = __float2bfloat16(f[i]);
        l[i] = __float2bfloat16(f[i] - __bfloat162float(h[i]));
    }
    __nv_bfloat16* base = g_bbar + (size_t)which * DMODEL * KEFF + (size_t)r * KEFF;
    *(__nv_bfloat162*)(base + k)          = __nv_bfloat162(h[0], h[1]);
    *(__nv_bfloat162*)(base + k + 2)      = __nv_bfloat162(h[2], h[3]);
    *(__nv_bfloat162*)(base + 1024 + k)   = __nv_bfloat162(h[0], h[1]);
    *(__nv_bfloat162*)(base + 1024 + k+2) = __nv_bfloat162(h[2], h[3]);
    *(__nv_bfloat162*)(base + 2048 + k)   = __nv_bfloat162(l[0], l[1]);
    *(__nv_bfloat162*)(base + 2048 + k+2) = __nv_bfloat162(l[2], l[3]);
}

// node 2: zero M accumulator
__global__ void zero_m()
{
    g_m[blockIdx.x * 256 + threadIdx.x] = 0.0f;
}

// ---------------------------------------------------------------------------
// nodes 3 & 6: mma.sync bf16 GEMM, Y = Abar @ Bbar[slab]^T + bias (opt. mask)
// CTA 128x128, BK=64, 8 warps (2x4), warp tile 64x32, 2-stage cp.async.
// mode 0: slabs 0,1 -> g_k (masked, +bk), g_v (+bv).  grid (8, 32, 2)
// mode 1: slab 2+batch -> out (+g_bias_ctx).          grid (8, 32, 1)
// ---------------------------------------------------------------------------
#define BKC 64
#define NITER (KEFF / BKC)   // 48
#define CHUNK_BYTES 16384    // 128 rows * 128B
#define BUF_BYTES   32768    // A chunk + B chunk

__global__ __launch_bounds__(256)
void qkv_mma(int mode,
             const float* __restrict__ amask,
             const float* __restrict__ bk,
             const float* __restrict__ bv,
             float* __restrict__ out)
{
    extern __shared__ __align__(1024) uint8_t smem[];
    __shared__ float sBias[128];

    const int tid  = threadIdx.x;
    const int wid  = tid >> 5;
    const int lane = tid & 31;
    const int m0 = blockIdx.y * 128;
    const int n0 = blockIdx.x * 128;

    int slab, ismask = 0;
    const float* bias;
    float* Y;
    if (mode == 0) {
        slab = blockIdx.z;
        if (slab == 0) { Y = g_k; bias = bk; ismask = 1; }
        else           { Y = g_v; bias = bv; }
    } else {
        const int b = (m0 >= SEQ) ? 1 : 0;
        slab = 2 + b;
        Y = out;
        bias = g_bias_ctx + b * DMODEL;
    }

    const __nv_bfloat16* __restrict__ Ag = g_abar;
    const __nv_bfloat16* __restrict__ Bg = g_bbar + (size_t)slab * DMODEL * KEFF;

    const uint32_t sbase = smem_to_u32(smem);

    if (tid < 128) sBias[tid] = bias[n0 + tid];

    // staging: 256 threads x 4 passes cover 1024 16B-chunks per matrix
    const int srow = tid >> 3;        // 0..31
    const int sc   = tid & 7;         // 16B chunk within 128B row

    auto stage = [&](int buf, int it) {
        const int ke = it * BKC;
        const uint32_t abase = sbase + buf * BUF_BYTES;
        const uint32_t bbase = abase + CHUNK_BYTES;
#pragma unroll
        for (int p = 0; p < 4; p++) {
            const int row = srow + p * 32;
            const uint32_t so = SWZ128((uint32_t)(row * 128 + sc * 16));
            CP_ASYNC16(abase + so, Ag + (size_t)(m0 + row) * KEFF + ke + sc * 8);
            CP_ASYNC16(bbase + so, Bg + (size_t)(n0 + row) * KEFF + ke + sc * 8);
        }
    };

    // warp tiling: 2 warps along M, 4 along N
    const int wm0 = (wid & 1) * 64;
    const int wn0 = (wid >> 1) * 32;

    float acc[16][4];
#pragma unroll
    for (int i = 0; i < 16; i++)
#pragma unroll
        for (int j = 0; j < 4; j++) acc[i][j] = 0.0f;

    const int a_row = wm0 + (lane & 15);
    const int a_ch  = (lane >> 4);
    const int b_g   = lane >> 3;
    const int b_row = wn0 + ((b_g >> 1) << 3) + (lane & 7);
    const int b_ch  = (b_g & 1);

    stage(0, 0);
    CP_COMMIT();

    for (int it = 0; it < NITER; it++) {
        if (it + 1 < NITER) {
            stage((it + 1) & 1, it + 1);
            CP_COMMIT();
            CP_WAIT1();
        } else {
            CP_WAIT0();
        }
        __syncthreads();

        const uint32_t abase = sbase + (it & 1) * BUF_BYTES;
        const uint32_t bbase = abase + CHUNK_BYTES;

#pragma unroll
        for (int ks = 0; ks < 4; ks++) {
            uint32_t a[4][4];
#pragma unroll
            for (int mi = 0; mi < 4; mi++) {
                const int row = a_row + mi * 16;
                const int ch  = ks * 2 + a_ch;
                ldsm_x4(a[mi][0], a[mi][1], a[mi][2], a[mi][3],
                        abase + SWZ128((uint32_t)(row * 128 + ch * 16)));
            }
            uint32_t b[2][4];
#pragma unroll
            for (int np = 0; np < 2; np++) {
                const int row = b_row + np * 16;
                const int ch  = ks * 2 + b_ch;
                ldsm_x4(b[np][0], b[np][1], b[np][2], b[np][3],
                        bbase + SWZ128((uint32_t)(row * 128 + ch * 16)));
            }
#pragma unroll
            for (int mi = 0; mi < 4; mi++)
#pragma unroll
                for (int ni = 0; ni < 4; ni++) {
                    const int np = ni >> 1, hf = (ni & 1) * 2;
                    mma_bf16(acc[mi * 4 + ni], a[mi][0], a[mi][1], a[mi][2], a[mi][3],
                             b[np][hf], b[np][hf + 1]);
                }
        }
        __syncthreads();
    }

    // Epilogue
    const int erow = wm0 + (lane >> 2);
    const int ecol = wn0 + (lane & 3) * 2;
#pragma unroll
    for (int mi = 0; mi < 4; mi++) {
        const int r0 = m0 + erow + mi * 16;
        const int r1 = r0 + 8;
        float mv0 = 1.0f, mv1 = 1.0f;
        if (ismask) {
            mv0 = (amask[r0] >= 0.0f) ? 1.0f : 0.0f;
            mv1 = (amask[r1] >= 0.0f) ? 1.0f : 0.0f;
        }
#pragma unroll
        for (int ni = 0; ni < 4; ni++) {
            const int c = ecol + ni * 8;
            float* p0 = Y + (size_t)r0 * DMODEL + n0 + c;
            float* p1 = Y + (size_t)r1 * DMODEL + n0 + c;
            float2 o0, o1;
            o0.x = (acc[mi * 4 + ni][0] + sBias[c + 0]) * mv0;
            o0.y = (acc[mi * 4 + ni][1] + sBias[c + 1]) * mv0;
            o1.x = (acc[mi * 4 + ni][2] + sBias[c + 0]) * mv1;
            o1.y = (acc[mi * 4 + ni][3] + sBias[c + 1]) * mv1;
            *(float2*)p0 = o0;
            *(float2*)p1 = o1;
        }
    }
}

// ---------------------------------------------------------------------------
// node 4: M[b,h] += K'[b,h]^T @ V[b,h] over a 128-key slice (split-K + atomics)
// grid = (32, 16), 256 threads
// ---------------------------------------------------------------------------
__global__ __launch_bounds__(256)
void kv_outer()
{
    const int bh = blockIdx.x;
    const int b = bh >> 4, h = bh & 15;
    const int kstart = blockIdx.y * 128;

    __shared__ float Ks[32][64];
    __shared__ float Vs[32][64];

    const int tid = threadIdx.x;
    const int tx = tid & 15, ty = tid >> 4;

    float acc[4][4];
#pragma unroll
    for (int i = 0; i < 4; i++)
#pragma unroll
        for (int j = 0; j < 4; j++) acc[i][j] = 0.0f;

    const int lr = tid >> 3;
    const int lc = (tid & 7) * 8;

    for (int kc = 0; kc < 4; kc++) {
        const size_t base = (size_t)(b * SEQ + kstart + kc * 32 + lr) * DMODEL + h * HDIM + lc;
        float4 k0 = *(const float4*)(g_k + base);
        float4 k1 = *(const float4*)(g_k + base + 4);
        Ks[lr][lc + 0] = k0.x; Ks[lr][lc + 1] = k0.y; Ks[lr][lc + 2] = k0.z; Ks[lr][lc + 3] = k0.w;
        Ks[lr][lc + 4] = k1.x; Ks[lr][lc + 5] = k1.y; Ks[lr][lc + 6] = k1.z; Ks[lr][lc + 7] = k1.w;
        float4 v0 = *(const float4*)(g_v + base);
        float4 v1 = *(const float4*)(g_v + base + 4);
        Vs[lr][lc + 0] = v0.x; Vs[lr][lc + 1] = v0.y; Vs[lr][lc + 2] = v0.z; Vs[lr][lc + 3] = v0.w;
        Vs[lr][lc + 4] = v1.x; Vs[lr][lc + 5] = v1.y; Vs[lr][lc + 6] = v1.z; Vs[lr][lc + 7] = v1.w;
        __syncthreads();

#pragma unroll
        for (int kk = 0; kk < 32; kk++) {
            float a[4], bb[4];
#pragma unroll
            for (int i = 0; i < 4; i++) a[i]  = Ks[kk][ty * 4 + i];
#pragma unroll
            for (int j = 0; j < 4; j++) bb[j] = Vs[kk][tx * 4 + j];
#pragma unroll
            for (int i = 0; i < 4; i++)
#pragma unroll
                for (int j = 0; j < 4; j++)
                    acc[i][j] += a[i] * bb[j];
        }
        __syncthreads();
    }

    float* Mout = g_m + (size_t)bh * HDIM * HDIM;
#pragma unroll
    for (int i = 0; i < 4; i++)
#pragma unroll
        for (int j = 0; j < 4; j++)
            atomicAdd(&Mout[(ty * 4 + i) * HDIM + tx * 4 + j], acc[i][j]);
}

// ---------------------------------------------------------------------------
// node 5: Bctx[b][n=h*64+j][k] = sum_c M[b,h][c][j] * Wq[h*64+c][k]
//         -> bf16 split into g_bbar slabs 2+b ; also bias_ctx = bq^T M
// grid (16 heads, 8 kblocks, 2 batch), 256 threads
// ---------------------------------------------------------------------------
__global__ __launch_bounds__(256)
void make_bctx(const float* __restrict__ Wq, const float* __restrict__ bq)
{
    const int h  = blockIdx.x;
    const int kb = blockIdx.y;
    const int b  = blockIdx.z;

    __shared__ float sM[64][64];    // 16KB  M[c][j]
    __shared__ float sW[64][128];   // 32KB  Wq[h*64+c][kb*128+kk]

    const int tid = threadIdx.x;

    // load M_h
    {
        const float* Msrc = g_m + (size_t)(b * NHEAD + h) * HDIM * HDIM;
        float* Md = &sM[0][0];
#pragma unroll
        for (int i = 0; i < 4; i++) {
            int idx = tid * 16 + i * 4;
            *(float4*)(Md + idx) = *(const float4*)(Msrc + idx);
        }
    }
    // load Wq tile: row c = tid>>2, 8 float4 per thread
    {
        const int c  = tid >> 2;
        const int f0 = (tid & 3) * 8;
        const float* Wr = Wq + (size_t)(h * 64 + c) * DMODEL + kb * 128;
#pragma unroll
        for (int i = 0; i < 8; i++)
            *(float4*)(&sW[c][f0 * 4 + i * 4]) = *(const float4*)(Wr + f0 * 4 + i * 4);
    }
    __syncthreads();

    // thread owns j = tid>>2, k-quarter = tid&3 (32 k values)
    const int j  = tid >> 2;
    const int kq = tid & 3;

    float acc[32];
#pragma unroll
    for (int i = 0; i < 32; i++) acc[i] = 0.0f;

#pragma unroll 4
    for (int c = 0; c < 64; c++) {
        const float mv = sM[c][j];
        const float4* wr = (const float4*)(&sW[c][kq * 32]);
#pragma unroll
        for (int q = 0; q < 8; q++) {
            float4 w = wr[q];
            acc[q * 4 + 0] += mv * w.x;
            acc[q * 4 + 1] += mv * w.y;
            acc[q * 4 + 2] += mv * w.z;
            acc[q * 4 + 3] += mv * w.w;
        }
    }

    // write split: slab 2+b, row n = h*64+j, cols kb*128 + kq*32 + [0,32)
    {
        __nv_bfloat16* base = g_bbar + (size_t)(2 + b) * DMODEL * KEFF
                            + (size_t)(h * 64 + j) * KEFF + kb * 128 + kq * 32;
#pragma unroll
        for (int i = 0; i < 32; i += 2) {
            __nv_bfloat16 h0 = __float2bfloat16(acc[i]);
            __nv_bfloat16 h1 = __float2bfloat16(acc[i + 1]);
            __nv_bfloat16 l0 = __float2bfloat16(acc[i]     - __bfloat162float(h0));
            __nv_bfloat16 l1 = __float2bfloat16(acc[i + 1] - __bfloat162float(h1));
            *(__nv_bfloat162*)(base + i)        = __nv_bfloat162(h0, h1);
            *(__nv_bfloat162*)(base + 1024 + i) = __nv_bfloat162(h0, h1);
            *(__nv_bfloat162*)(base + 2048 + i) = __nv_bfloat162(l0, l1);
        }
    }

    // bias_ctx (kb==0 only): threads 0..63 compute sum_c bq[h64+c]*M[c][j]
    if (kb == 0 && tid < 64) {
        float s = 0.0f;
#pragma unroll 8
        for (int c = 0; c < 64; c++) s += bq[h * 64 + c] * sM[c][tid];
        g_bias_ctx[b * DMODEL + h * 64 + tid] = s;
    }
}

// ---------------------------------------------------------------------------
extern "C" void kernel_launch(void* const* d_in, const int* in_sizes, int n_in,
                              void* d_out, int out_size)
{
    const float* X     = (const float*)d_in[0];
    const float* amask = (const float*)d_in[1];
    const float* Wq    = (const float*)d_in[2];
    const float* bq    = (const float*)d_in[3];
    const float* Wk    = (const float*)d_in[4];
    const float* bk    = (const float*)d_in[5];
    const float* Wv    = (const float*)d_in[6];
    const float* bv    = (const float*)d_in[7];
    float* out = (float*)d_out;

    cudaFuncSetAttribute(qkv_mma, cudaFuncAttributeMaxDynamicSharedMemorySize,
                         2 * BUF_BYTES);

    conv_x<<<ELEMS / 4 / 256, 256>>>(X);                                  // node 0
    conv_w<<<dim3(DMODEL * DMODEL / 4 / 256, 2), 256>>>(Wk, Wv);          // node 1
    zero_m<<<(BATCH * NHEAD * HDIM * HDIM) / 256, 256>>>();               // node 2
    qkv_mma<<<dim3(8, 32, 2), 256, 2 * BUF_BYTES>>>(0, amask, bk, bv, out);  // node 3 (profiled)
    kv_outer<<<dim3(BATCH * NHEAD, 16), 256>>>();                         // node 4
    make_bctx<<<dim3(NHEAD, 8, BATCH), 256>>>(Wq, bq);                    // node 5
    qkv_mma<<<dim3(8, 32, 1), 256, 2 * BUF_BYTES>>>(1, amask, bk, bv, out); // node 6
}

// round 6
// speedup vs baseline: 1.4119x; 1.4119x over previous
#include <cuda_runtime.h>
#include <cuda_bf16.h>
#include <cstdint>

// Problem constants
#define BATCH 2
#define SEQ   2048
#define DMODEL 1024
#define NHEAD 16
#define HDIM  64
#define ROWS  (BATCH*SEQ)          // 4096
#define ELEMS (ROWS*DMODEL)        // 4,194,304
#define KEFF  3072                 // 3-term bf16 split K

// Scratch (static __device__ globals — allocation-free per harness rules)
__device__ float g_q[ELEMS];
__device__ float g_k[ELEMS];   // masked K (K')
__device__ float g_v[ELEMS];
__device__ float g_m[BATCH*NHEAD*HDIM*HDIM];   // 131072 floats
__device__ __nv_bfloat16 g_abar[(size_t)ROWS*KEFF];       // [4096,3072] 24MB
__device__ __nv_bfloat16 g_bbar[(size_t)3*DMODEL*KEFF];   // 3x[1024,3072] 18MB

// ---------------------------------------------------------------------------
// Base-target (sm_80+) PTX helpers: ldmatrix / mma.sync / cp.async
// ---------------------------------------------------------------------------
__device__ __forceinline__ uint32_t smem_to_u32(const void* p) {
    uint32_t a;
    asm("{ .reg .u64 t; cvta.to.shared.u64 t, %1; cvt.u32.u64 %0, t; }" : "=r"(a) : "l"(p));
    return a;
}
__device__ __forceinline__ void ldsm_x4(uint32_t& r0, uint32_t& r1, uint32_t& r2, uint32_t& r3,
                                        uint32_t addr) {
    asm volatile("ldmatrix.sync.aligned.m8n8.x4.shared.b16 {%0,%1,%2,%3}, [%4];"
                 : "=r"(r0), "=r"(r1), "=r"(r2), "=r"(r3) : "r"(addr));
}
__device__ __forceinline__ void mma_bf16(float* d, uint32_t a0, uint32_t a1, uint32_t a2,
                                         uint32_t a3, uint32_t b0, uint32_t b1) {
    asm volatile("mma.sync.aligned.m16n8k16.row.col.f32.bf16.bf16.f32 "
                 "{%0,%1,%2,%3}, {%4,%5,%6,%7}, {%8,%9}, {%0,%1,%2,%3};"
                 : "+f"(d[0]), "+f"(d[1]), "+f"(d[2]), "+f"(d[3])
                 : "r"(a0), "r"(a1), "r"(a2), "r"(a3), "r"(b0), "r"(b1));
}
#define CP_ASYNC16(saddr, gptr) \
    asm volatile("cp.async.cg.shared.global [%0], [%1], 16;" :: "r"(saddr), "l"(gptr))
#define CP_COMMIT() asm volatile("cp.async.commit_group;" ::: "memory")
#define CP_WAIT1()  asm volatile("cp.async.wait_group 1;" ::: "memory")
#define CP_WAIT0()  asm volatile("cp.async.wait_group 0;" ::: "memory")

// SW128 swizzle: rows of 128B, chunk16B index ^= (row & 7)
#define SWZ128(bo) ((bo) ^ (((bo) >> 3) & 0x70))

// ---------------------------------------------------------------------------
// node 0: X -> Abar = [hi | lo | hi] along K (bf16 split)
// ---------------------------------------------------------------------------
__global__ __launch_bounds__(256) void conv_x(const float* __restrict__ X)
{
    int t = blockIdx.x * 256 + threadIdx.x;
    int idx = t * 4;
    float4 v = *(const float4*)(X + idx);
    int r = idx >> 10, k = idx & 1023;
    float f[4] = {v.x, v.y, v.z, v.w};
    __nv_bfloat16 h[4], l[4];
#pragma unroll
    for (int i = 0; i < 4; i++) {
        h[i] = __float2bfloat16(f[i]);
        l[i] = __float2bfloat16(f[i] - __bfloat162float(h[i]));
    }
    __nv_bfloat16* base = g_abar + (size_t)r * KEFF;
    *(__nv_bfloat162*)(base + k)          = __nv_bfloat162(h[0], h[1]);
    *(__nv_bfloat162*)(base + k + 2)      = __nv_bfloat162(h[2], h[3]);
    *(__nv_bfloat162*)(base + 1024 + k)   = __nv_bfloat162(l[0], l[1]);
    *(__nv_bfloat162*)(base + 1024 + k+2) = __nv_bfloat162(l[2], l[3]);
    *(__nv_bfloat162*)(base + 2048 + k)   = __nv_bfloat162(h[0], h[1]);
    *(__nv_bfloat162*)(base + 2048 + k+2) = __nv_bfloat162(h[2], h[3]);
}

// node 1: W -> Bbar = [hi | hi | lo]
__global__ __launch_bounds__(256) void conv_w(const float* __restrict__ Wq,
                                              const float* __restrict__ Wk,
                                              const float* __restrict__ Wv)
{
    int which = blockIdx.y;
    const float* __restrict__ W = (which == 0) ? Wq : (which == 1) ? Wk : Wv;
    int t = blockIdx.x * 256 + threadIdx.x;
    int idx = t * 4;
    float4 v = *(const float4*)(W + idx);
    int r = idx >> 10, k = idx & 1023;
    float f[4] = {v.x, v.y, v.z, v.w};
    __nv_bfloat16 h[4], l[4];
#pragma unroll
    for (int i = 0; i < 4; i++) {
        h[i] = __float2bfloat16(f[i]);
        l[i] = __float2bfloat16(f[i] - __bfloat162float(h[i]));
    }
    __nv_bfloat16* base = g_bbar + (size_t)which * DMODEL * KEFF + (size_t)r * KEFF;
    *(__nv_bfloat162*)(base + k)          = __nv_bfloat162(h[0], h[1]);
    *(__nv_bfloat162*)(base + k + 2)      = __nv_bfloat162(h[2], h[3]);
    *(__nv_bfloat162*)(base + 1024 + k)   = __nv_bfloat162(h[0], h[1]);
    *(__nv_bfloat162*)(base + 1024 + k+2) = __nv_bfloat162(h[2], h[3]);
    *(__nv_bfloat162*)(base + 2048 + k)   = __nv_bfloat162(l[0], l[1]);
    *(__nv_bfloat162*)(base + 2048 + k+2) = __nv_bfloat162(l[2], l[3]);
}

// node 2: zero M accumulator
__global__ void zero_m()
{
    g_m[blockIdx.x * 256 + threadIdx.x] = 0.0f;
}

// ---------------------------------------------------------------------------
// node 3: mma.sync bf16 QKV projection. Y = Abar @ Bbar^T + bias (+ mask for K)
// CTA 128x128, BK=64, 8 warps (2x4), warp tile 64x32, 2-stage cp.async,
// __launch_bounds__(256, 2) to force 2 CTAs/SM (reg cap 128).
// grid = (8, 32, 3), dynamic smem = 64KB
// ---------------------------------------------------------------------------
#define BKC 64
#define NITER (KEFF / BKC)   // 48
#define CHUNK_BYTES 16384    // 128 rows * 128B
#define BUF_BYTES   32768    // A chunk + B chunk

__global__ __launch_bounds__(256, 2)
void qkv_mma(const float* __restrict__ amask,
             const float* __restrict__ bq,
             const float* __restrict__ bk,
             const float* __restrict__ bv)
{
    extern __shared__ __align__(1024) uint8_t smem[];
    __shared__ float sBias[128];

    const int tid  = threadIdx.x;
    const int wid  = tid >> 5;
    const int lane = tid & 31;
    const int which = blockIdx.z;
    const int m0 = blockIdx.y * 128;
    const int n0 = blockIdx.x * 128;

    const float* __restrict__ bias = (which == 0) ? bq : (which == 1) ? bk : bv;
    float* __restrict__ Y          = (which == 0) ? g_q : (which == 1) ? g_k : g_v;

    const __nv_bfloat16* __restrict__ Ag = g_abar;
    const __nv_bfloat16* __restrict__ Bg = g_bbar + (size_t)which * DMODEL * KEFF;

    const uint32_t sbase = smem_to_u32(smem);

    if (tid < 128) sBias[tid] = bias[n0 + tid];

    // staging: 256 threads x 4 passes cover 1024 16B-chunks per matrix
    const int srow = tid >> 3;        // 0..31
    const int sc   = tid & 7;         // 16B chunk within 128B row

    auto stage = [&](int buf, int it) {
        const int ke = it * BKC;
        const uint32_t abase = sbase + buf * BUF_BYTES;
        const uint32_t bbase = abase + CHUNK_BYTES;
#pragma unroll
        for (int p = 0; p < 4; p++) {
            const int row = srow + p * 32;
            const uint32_t so = SWZ128((uint32_t)(row * 128 + sc * 16));
            CP_ASYNC16(abase + so, Ag + (size_t)(m0 + row) * KEFF + ke + sc * 8);
            CP_ASYNC16(bbase + so, Bg + (size_t)(n0 + row) * KEFF + ke + sc * 8);
        }
    };

    // warp tiling: 2 warps along M, 4 along N
    const int wm0 = (wid & 1) * 64;
    const int wn0 = (wid >> 1) * 32;

    float acc[16][4];
#pragma unroll
    for (int i = 0; i < 16; i++)
#pragma unroll
        for (int j = 0; j < 4; j++) acc[i][j] = 0.0f;

    const int a_row = wm0 + (lane & 15);
    const int a_ch  = (lane >> 4);
    const int b_g   = lane >> 3;
    const int b_row = wn0 + ((b_g >> 1) << 3) + (lane & 7);
    const int b_ch  = (b_g & 1);

    stage(0, 0);
    CP_COMMIT();

    for (int it = 0; it < NITER; it++) {
        if (it + 1 < NITER) {
            stage((it + 1) & 1, it + 1);
            CP_COMMIT();
            CP_WAIT1();
        } else {
            CP_WAIT0();
        }
        __syncthreads();

        const uint32_t abase = sbase + (it & 1) * BUF_BYTES;
        const uint32_t bbase = abase + CHUNK_BYTES;

#pragma unroll
        for (int ks = 0; ks < 4; ks++) {
            uint32_t a[4][4];
#pragma unroll
            for (int mi = 0; mi < 4; mi++) {
                const int row = a_row + mi * 16;
                const int ch  = ks * 2 + a_ch;
                ldsm_x4(a[mi][0], a[mi][1], a[mi][2], a[mi][3],
                        abase + SWZ128((uint32_t)(row * 128 + ch * 16)));
            }
            uint32_t b[2][4];
#pragma unroll
            for (int np = 0; np < 2; np++) {
                const int row = b_row + np * 16;
                const int ch  = ks * 2 + b_ch;
                ldsm_x4(b[np][0], b[np][1], b[np][2], b[np][3],
                        bbase + SWZ128((uint32_t)(row * 128 + ch * 16)));
            }
#pragma unroll
            for (int mi = 0; mi < 4; mi++)
#pragma unroll
                for (int ni = 0; ni < 4; ni++) {
                    const int np = ni >> 1, hf = (ni & 1) * 2;
                    mma_bf16(acc[mi * 4 + ni], a[mi][0], a[mi][1], a[mi][2], a[mi][3],
                             b[np][hf], b[np][hf + 1]);
                }
        }
        __syncthreads();
    }

    // Epilogue
    const int erow = wm0 + (lane >> 2);
    const int ecol = wn0 + (lane & 3) * 2;
#pragma unroll
    for (int mi = 0; mi < 4; mi++) {
        const int r0 = m0 + erow + mi * 16;
        const int r1 = r0 + 8;
        float mv0 = 1.0f, mv1 = 1.0f;
        if (which == 1) {
            mv0 = (amask[r0] >= 0.0f) ? 1.0f : 0.0f;
            mv1 = (amask[r1] >= 0.0f) ? 1.0f : 0.0f;
        }
#pragma unroll
        for (int ni = 0; ni < 4; ni++) {
            const int c = ecol + ni * 8;
            float* p0 = Y + (size_t)r0 * DMODEL + n0 + c;
            float* p1 = Y + (size_t)r1 * DMODEL + n0 + c;
            float2 o0, o1;
            o0.x = (acc[mi * 4 + ni][0] + sBias[c + 0]) * mv0;
            o0.y = (acc[mi * 4 + ni][1] + sBias[c + 1]) * mv0;
            o1.x = (acc[mi * 4 + ni][2] + sBias[c + 0]) * mv1;
            o1.y = (acc[mi * 4 + ni][3] + sBias[c + 1]) * mv1;
            *(float2*)p0 = o0;
            *(float2*)p1 = o1;
        }
    }
}

// ---------------------------------------------------------------------------
// node 4: M[b,h] += K'[b,h]^T @ V[b,h] over a 128-key slice (split-K + atomics)
// grid = (32, 16), 256 threads
// ---------------------------------------------------------------------------
__global__ __launch_bounds__(256)
void kv_outer()
{
    const int bh = blockIdx.x;
    const int b = bh >> 4, h = bh & 15;
    const int kstart = blockIdx.y * 128;

    __shared__ float Ks[32][64];
    __shared__ float Vs[32][64];

    const int tid = threadIdx.x;
    const int tx = tid & 15, ty = tid >> 4;

    float acc[4][4];
#pragma unroll
    for (int i = 0; i < 4; i++)
#pragma unroll
        for (int j = 0; j < 4; j++) acc[i][j] = 0.0f;

    const int lr = tid >> 3;
    const int lc = (tid & 7) * 8;

    for (int kc = 0; kc < 4; kc++) {
        const size_t base = (size_t)(b * SEQ + kstart + kc * 32 + lr) * DMODEL + h * HDIM + lc;
        float4 k0 = *(const float4*)(g_k + base);
        float4 k1 = *(const float4*)(g_k + base + 4);
        Ks[lr][lc + 0] = k0.x; Ks[lr][lc + 1] = k0.y; Ks[lr][lc + 2] = k0.z; Ks[lr][lc + 3] = k0.w;
        Ks[lr][lc + 4] = k1.x; Ks[lr][lc + 5] = k1.y; Ks[lr][lc + 6] = k1.z; Ks[lr][lc + 7] = k1.w;
        float4 v0 = *(const float4*)(g_v + base);
        float4 v1 = *(const float4*)(g_v + base + 4);
        Vs[lr][lc + 0] = v0.x; Vs[lr][lc + 1] = v0.y; Vs[lr][lc + 2] = v0.z; Vs[lr][lc + 3] = v0.w;
        Vs[lr][lc + 4] = v1.x; Vs[lr][lc + 5] = v1.y; Vs[lr][lc + 6] = v1.z; Vs[lr][lc + 7] = v1.w;
        __syncthreads();

#pragma unroll
        for (int kk = 0; kk < 32; kk++) {
            float a[4], bb[4];
#pragma unroll
            for (int i = 0; i < 4; i++) a[i]  = Ks[kk][ty * 4 + i];
#pragma unroll
            for (int j = 0; j < 4; j++) bb[j] = Vs[kk][tx * 4 + j];
#pragma unroll
            for (int i = 0; i < 4; i++)
#pragma unroll
                for (int j = 0; j < 4; j++)
                    acc[i][j] += a[i] * bb[j];
        }
        __syncthreads();
    }

    float* Mout = g_m + (size_t)bh * HDIM * HDIM;
#pragma unroll
    for (int i = 0; i < 4; i++)
#pragma unroll
        for (int j = 0; j < 4; j++)
            atomicAdd(&Mout[(ty * 4 + i) * HDIM + tx * 4 + j], acc[i][j]);
}

// ---------------------------------------------------------------------------
// node 5: ctx = Q @ M
// ---------------------------------------------------------------------------
__global__ __launch_bounds__(256)
void ctx_gemm(float* __restrict__ out)
{
    const int st = blockIdx.x, h = blockIdx.y, b = blockIdx.z;
    const int s0 = st * 64;

    __shared__ float Ms[64][64];
    __shared__ float Qt[64][72];

    const int tid = threadIdx.x;

    {
        const float* Msrc = g_m + (size_t)(b * NHEAD + h) * HDIM * HDIM;
        float* Md = &Ms[0][0];
#pragma unroll
        for (int i = 0; i < 4; i++) {
            int idx = tid * 16 + i * 4;
            *(float4*)(Md + idx) = *(const float4*)(Msrc + idx);
        }
    }
    {
        const int row = tid >> 2;
        const int cg  = (tid & 3) * 16;
        const size_t base = (size_t)(b * SEQ + s0 + row) * DMODEL + h * HDIM + cg;
#pragma unroll
        for (int i = 0; i < 4; i++) {
            float4 q = *(const float4*)(g_q + base + i * 4);
            Qt[cg + i * 4 + 0][row] = q.x;
            Qt[cg + i * 4 + 1][row] = q.y;
            Qt[cg + i * 4 + 2][row] = q.z;
            Qt[cg + i * 4 + 3][row] = q.w;
        }
    }
    __syncthreads();

    const int tx = tid & 15, ty = tid >> 4;
    float acc[4][4];
#pragma unroll
    for (int i = 0; i < 4; i++)
#pragma unroll
        for (int j = 0; j < 4; j++) acc[i][j] = 0.0f;

#pragma unroll
    for (int k = 0; k < 64; k++) {
        float a[4], bb[4];
#pragma unroll
        for (int i = 0; i < 4; i++) a[i]  = Qt[k][ty * 4 + i];
#pragma unroll
        for (int j = 0; j < 4; j++) bb[j] = Ms[k][tx * 4 + j];
#pragma unroll
        for (int i = 0; i < 4; i++)
#pragma unroll
            for (int j = 0; j < 4; j++)
                acc[i][j] += a[i] * bb[j];
    }

#pragma unroll
    for (int i = 0; i < 4; i++) {
        const int srow = s0 + ty * 4 + i;
#pragma unroll
        for (int j = 0; j < 4; j++) {
            const int col = h * HDIM + tx * 4 + j;
            out[(size_t)(b * SEQ + srow) * DMODEL + col] = acc[i][j];
        }
    }
}

// ---------------------------------------------------------------------------
extern "C" void kernel_launch(void* const* d_in, const int* in_sizes, int n_in,
                              void* d_out, int out_size)
{
    const float* X     = (const float*)d_in[0];
    const float* amask = (const float*)d_in[1];
    const float* Wq    = (const float*)d_in[2];
    const float* bq    = (const float*)d_in[3];
    const float* Wk    = (const float*)d_in[4];
    const float* bk    = (const float*)d_in[5];
    const float* Wv    = (const float*)d_in[6];
    const float* bv    = (const float*)d_in[7];
    float* out = (float*)d_out;

    cudaFuncSetAttribute(qkv_mma, cudaFuncAttributeMaxDynamicSharedMemorySize,
                         2 * BUF_BYTES);

    conv_x<<<ELEMS / 4 / 256, 256>>>(X);                                  // node 0
    conv_w<<<dim3(DMODEL * DMODEL / 4 / 256, 3), 256>>>(Wq, Wk, Wv);      // node 1
    zero_m<<<(BATCH * NHEAD * HDIM * HDIM) / 256, 256>>>();               // node 2
    qkv_mma<<<dim3(8, 32, 3), 256, 2 * BUF_BYTES>>>(amask, bq, bk, bv);   // node 3 (profiled)
    kv_outer<<<dim3(BATCH * NHEAD, 16), 256>>>();                         // node 4
    ctx_gemm<<<dim3(SEQ / 64, NHEAD, BATCH), 256>>>(out);                 // node 5
}